// round 6
// baseline (speedup 1.0000x reference)
#include <cuda_runtime.h>

#define TSTEPS 2048
#define BSIZE  8192
#define HH     0.01f
#define NG     (TSTEPS / 4)   // 512 groups of 4 steps
#define PD     4              // prefetch distance (groups)

__device__ __forceinline__ float tanh_approx(float x) {
    float y; asm("tanh.approx.f32 %0, %1;" : "=f"(y) : "f"(x)); return y;
}

struct Consts {
    // S = symmetric matrix of the (tanh-halved) quadratic form
    float S11, S12, S13, S14, S22, S23, S24, S33, S34, S44;
    float b1, b2, b3, b4, cc;           // linear part, constant
    float nb12, nb3, nb4;               // -(b1+b2), -b3, -b4 (beta path)
    float P1, P2, P3, u33, u34, u44;    // gamma combos
    float A1, A2, B1, B2, q1, q2, dC;   // bx linear form
    float K1, K2;                       // cost
};

// One step. phi is loop-carried; chain = tanh + 2 FMA.
// ADDSC: accumulate stage cost (skipped only for i = T-1).
template<bool ADDSC>
__device__ __forceinline__ void step(const Consts& c, float w1, float w2,
                                     float& x1, float& x2, float& h1, float& h2,
                                     float& phi, float& accQ, float& accR,
                                     float& accT)
{
    const float C1 = 0.5f * HH * HH;   // +h^2/2 (collapsed RK4, x1 eq)

    float t = tanh_approx(phi);        // delta = 0.5 + 0.5*t

    if (ADDSC) {
        accQ = fmaf(x1, x1, accQ);
        accQ = fmaf(x2, x2, accQ);
        float kx = fmaf(c.K2, x2, c.K1 * x1);   // u_s = K · x
        accR = fmaf(kx, kx, accR);
        accT = accT + t;
    }

    // ---- geometry (pre-tanh quantities of THIS step) ----
    float dx1 = x1 - h1, dx2 = x2 - h2;
    float dh1 = 0.5f * dx1, dh2 = 0.5f * dx2;
    float hm1 = h1 + dh1,   hm2 = h2 + dh2;
    float g   = fmaf(c.q2, dx2, c.q1 * dx1);            // 0.005 * K · dx
    float hb  = fmaf(c.q1, h1, fmaf(c.q2, h2, C1));     // q·h + C1
    float wb1 = w1 + hb;
    float wb2 = w2 + (hb + c.dC);
    float bx1 = fmaf(c.A1, x1, fmaf(c.A2, x2, wb1));
    float bx2 = fmaf(c.B1, x1, fmaf(c.B2, x2, wb2));
    // zm = (bx1, bx2, hm1, hm2), d = (g, g, dh1, dh2); z' = zm + t*d

    // ---- v = S*zm + b  (hm innermost: ready earlier) ----
    float v1 = fmaf(c.S11,bx1, fmaf(c.S12,bx2, fmaf(c.S13,hm1, fmaf(c.S14,hm2, c.b1))));
    float v2 = fmaf(c.S12,bx1, fmaf(c.S22,bx2, fmaf(c.S23,hm1, fmaf(c.S24,hm2, c.b2))));
    float v3 = fmaf(c.S13,bx1, fmaf(c.S23,bx2, fmaf(c.S33,hm1, fmaf(c.S34,hm2, c.b3))));
    float v4 = fmaf(c.S14,bx1, fmaf(c.S24,bx2, fmaf(c.S34,hm1, fmaf(c.S44,hm2, c.b4))));

    // alpha = Q(zm) = zm·v + cc
    float alpha = fmaf(bx1,v1, fmaf(bx2,v2, fmaf(hm1,v3, fmaf(hm2,v4, c.cc))));

    // beta = d·(2v - b)
    float v12 = v1 + v2;
    float s12 = fmaf(2.0f, v12, c.nb12);
    float s3  = fmaf(2.0f, v3,  c.nb3);
    float s4  = fmaf(2.0f, v4,  c.nb4);
    float beta = fmaf(dh2, s4, fmaf(dh1, s3, g * s12));

    // gamma = Qq(d)
    float ta = fmaf(dh2, c.P3, dh1 * c.P2);
    float tb = fmaf(g, c.P1, ta);
    float gg = g * tb;
    float f2 = fmaf(c.u33, dh1, c.u34 * dh2);
    float f3 = dh1 * f2;
    float f4 = c.u44 * dh2;
    float f5 = f3 + gg;
    float gamma = fmaf(f4, dh2, f5);

    // ---- advance state and phi (the only t-dependent chain) ----
    x1 = fmaf(t, g,   bx1);
    x2 = fmaf(t, g,   bx2);
    h1 = fmaf(t, dh1, hm1);
    h2 = fmaf(t, dh2, hm2);
    phi = fmaf(t, fmaf(gamma, t, beta), alpha);
}

__global__ void __launch_bounds__(64, 1) cstr_traj_kernel(
    const float* __restrict__ w,   // (B, 2, T)
    const float* __restrict__ K,   // (1, 2)
    const float* __restrict__ L,   // (4, 4)
    const float* __restrict__ M,   // (1, 4)
    const float* __restrict__ Mo,  // (1, 1)
    float* __restrict__ out)       // (B,)
{
    int b = blockIdx.x * blockDim.x + threadIdx.x;

    const float s = 0.5f;  // sigmoid(phi) = 0.5 + 0.5*tanh(0.5*phi)
    Consts c;
    c.K1 = __ldg(K);  c.K2 = __ldg(K + 1);
    float l[16];
#pragma unroll
    for (int i = 0; i < 16; i++) l[i] = __ldg(L + i);
    // upper-triangular coeffs of the tanh-halved quadratic form
    float u11 = s * l[0],           u22 = s * l[5];
    float u33 = s * l[10],          u44 = s * l[15];
    float u12 = s * (l[1] + l[4]),  u13 = s * (l[2] + l[8]);
    float u14 = s * (l[3] + l[12]), u23 = s * (l[6] + l[9]);
    float u24 = s * (l[7] + l[13]), u34 = s * (l[11] + l[14]);
    c.S11 = u11; c.S22 = u22; c.S33 = u33; c.S44 = u44;
    c.S12 = 0.5f * u12; c.S13 = 0.5f * u13; c.S14 = 0.5f * u14;
    c.S23 = 0.5f * u23; c.S24 = 0.5f * u24; c.S34 = 0.5f * u34;
    c.b1 = s * __ldg(M);     c.b2 = s * __ldg(M + 1);
    c.b3 = s * __ldg(M + 2); c.b4 = s * __ldg(M + 3);
    c.cc = s * __ldg(Mo);
    c.nb12 = -(c.b1 + c.b2); c.nb3 = -c.b3; c.nb4 = -c.b4;
    c.P1 = u11 + u12 + u22;  c.P2 = u13 + u23;  c.P3 = u14 + u24;
    c.u33 = u33; c.u34 = u34; c.u44 = u44;
    c.q1 = 0.005f * c.K1;    c.q2 = 0.005f * c.K2;     // 0.5*HH*K
    c.A1 = 0.98f + c.q1;     c.A2 = 0.01f + c.q2;
    c.B1 = 0.01f + c.q1;     c.B2 = 0.98f + c.q2;
    c.dC = (-HH * HH) - (0.5f * HH * HH);               // C2 - C1

    const float4* w0 = (const float4*)(w + (size_t)b * 2 * TSTEPS);
    const float4* w1 = (const float4*)(w + (size_t)b * 2 * TSTEPS + TSTEPS);

    float x1 = 1.0f, x2 = 0.0f, h1 = 1.0f, h2 = 0.0f;
    float accQ = 0.0f, accR = 0.0f, accT = 0.0f;
    // Step 0: reference forces delta=1 and x_hat frozen. Since x==h at i=0,
    // d = 0 makes t dynamically inert; set phi so t=1 -> delta=1 exactly.
    float phi = 30.0f;

    // ---- software prefetch pipeline: PD groups in registers ----
    float4 bA[PD], bB[PD];
#pragma unroll
    for (int d = 0; d < PD; ++d) { bA[d] = w0[d]; bB[d] = w1[d]; }

    // Main: base = 0,4,...,NG-2PD; consume groups base..base+3, prefetch +PD.
    // (NG-PD = 508, base runs to 504; all slot indices static after unroll.)
    for (int base = 0; base < NG - PD; base += PD) {
#pragma unroll
        for (int d = 0; d < PD; ++d) {
            float4 wa = bA[d], wb = bB[d];
            bA[d] = w0[base + PD + d];
            bB[d] = w1[base + PD + d];
            step<true>(c, wa.x, wb.x, x1, x2, h1, h2, phi, accQ, accR, accT);
            step<true>(c, wa.y, wb.y, x1, x2, h1, h2, phi, accQ, accR, accT);
            step<true>(c, wa.z, wb.z, x1, x2, h1, h2, phi, accQ, accR, accT);
            step<true>(c, wa.w, wb.w, x1, x2, h1, h2, phi, accQ, accR, accT);
        }
    }

    // Tail: groups NG-PD .. NG-1 from the buffers (static slots)
#pragma unroll
    for (int d = 0; d < PD - 1; ++d) {
        float4 wa = bA[d], wb = bB[d];
        step<true>(c, wa.x, wb.x, x1, x2, h1, h2, phi, accQ, accR, accT);
        step<true>(c, wa.y, wb.y, x1, x2, h1, h2, phi, accQ, accR, accT);
        step<true>(c, wa.z, wb.z, x1, x2, h1, h2, phi, accQ, accR, accT);
        step<true>(c, wa.w, wb.w, x1, x2, h1, h2, phi, accQ, accR, accT);
    }
    {   // last group: final step (i = T-1) updates state, adds no stage cost
        float4 wa = bA[PD - 1], wb = bB[PD - 1];
        step<true >(c, wa.x, wb.x, x1, x2, h1, h2, phi, accQ, accR, accT);
        step<true >(c, wa.y, wb.y, x1, x2, h1, h2, phi, accQ, accR, accT);
        step<true >(c, wa.z, wb.z, x1, x2, h1, h2, phi, accQ, accR, accT);
        step<false>(c, wa.w, wb.w, x1, x2, h1, h2, phi, accQ, accR, accT);
    }

    // J = sum x^T x + 0.1 sum u_s^2 + sum delta + terminal 10*|x_T|^2
    // sum delta over 2047 stage costs = 2047*0.5 + 0.5*sum t
    float J = accQ;
    J = fmaf(0.1f, accR, J);
    J = fmaf(0.5f, accT, J);
    J = J + 1023.5f;
    J = fmaf(10.0f * x1, x1, J);
    J = fmaf(10.0f * x2, x2, J);

    if (b < BSIZE) out[b] = J;
}

extern "C" void kernel_launch(void* const* d_in, const int* in_sizes, int n_in,
                              void* d_out, int out_size)
{
    const float* w  = (const float*)d_in[0];
    const float* K  = (const float*)d_in[1];
    const float* L  = (const float*)d_in[2];
    const float* M  = (const float*)d_in[3];
    const float* Mo = (const float*)d_in[4];
    float* out = (float*)d_out;

    cstr_traj_kernel<<<BSIZE / 64, 64>>>(w, K, L, M, Mo, out);
}

// round 8
// speedup vs baseline: 1.0808x; 1.0808x over previous
#include <cuda_runtime.h>

#define TSTEPS 2048
#define BSIZE  8192
#define HH     0.01f
#define NG     (TSTEPS / 4)   // 512 groups of 4 steps
#define PD     4              // prefetch distance (groups)

typedef unsigned long long u64;

__device__ __forceinline__ float tanh_approx(float x) {
    float y; asm("tanh.approx.f32 %0, %1;" : "=f"(y) : "f"(x)); return y;
}
__device__ __forceinline__ u64 pk(float lo, float hi) {
    u64 r; asm("mov.b64 %0, {%1, %2};" : "=l"(r) : "f"(lo), "f"(hi)); return r;
}
__device__ __forceinline__ void upk(float& lo, float& hi, u64 v) {
    asm("mov.b64 {%0, %1}, %2;" : "=f"(lo), "=f"(hi) : "l"(v));
}
__device__ __forceinline__ u64 fma2(u64 a, u64 b, u64 c) {
    u64 d; asm("fma.rn.f32x2 %0, %1, %2, %3;" : "=l"(d) : "l"(a), "l"(b), "l"(c)); return d;
}
__device__ __forceinline__ u64 add2(u64 a, u64 b) {
    u64 d; asm("add.rn.f32x2 %0, %1, %2;" : "=l"(d) : "l"(a), "l"(b)); return d;
}
__device__ __forceinline__ u64 mul2(u64 a, u64 b) {
    u64 d; asm("mul.rn.f32x2 %0, %1, %2;" : "=l"(d) : "l"(a), "l"(b)); return d;
}

struct CP {
    // packed constants
    u64 NEG1, HALF, E2, HH2, Cp;
    u64 A_x1, A_x2, A_h1, A_h2, Bm12;   // (q1,q2) column pairs
    u64 A3_h1, A3_h2, Bm34;             // (q3,q4) column pairs (NO bm0 here)
    u64 Cbm0;                           // (bm0, 0) — affine constant of phi
    // scalars
    float K1, K2, q1, q2;               // q = 0.005*K
};

// One step, R4 formulation, f32x2-packed.
// u = K·xh_new = [kuh + 0.5 K·dx] + 0.5 K·dx · t ;  x' = BX + g·t, g = 0.005 K·dx
template<bool FIRST, bool ADDSC>
__device__ __forceinline__ void stepP(const CP& c, float w1, float w2,
                                      u64& X, u64& Hh,
                                      u64& accQ2, float& accR, float& accT)
{
    float x1, x2, h1, h2;
    upk(x1, x2, X); upk(h1, h2, Hh);

    // ---- geometry (packed) ----
    u64 DX = fma2(Hh, c.NEG1, X);          // (dx1, dx2) = X - H
    float dx1, dx2; upk(dx1, dx2, DX);
    u64 DH = mul2(DX, c.HALF);             // (0.5 dx)
    u64 HM = add2(Hh, DH);                 // midpoint of estimator update

    float kuh = fmaf(c.K2, h2, c.K1 * h1);          // K · x_hat
    float g   = fmaf(c.q2, dx2, c.q1 * dx1);        // 0.005 * K · dx
    float bb  = fmaf(0.01f, kuh, g);                // HH*(K·xh + 0.5 K·dx)

    u64 W  = pk(w1, w2);
    u64 WC = add2(W, c.Cp);
    u64 Xs = pk(x2, x1);                   // swapped halves
    u64 T1 = fma2(X, c.E2, WC);
    u64 BASE = fma2(Xs, c.HH2, T1);        // collapsed-RK4 linear part
    u64 BB = pk(bb, bb);
    u64 BX = add2(BASE, BB);

    // ---- phi tree (packed, 3 levels) ----
    // phi = x1*q1 + x2*q2 + h1*q3 + h2*q4 + bm0 ; bm_i live INSIDE q_i
    // (multiplied by z_i = the M·z term); bm0 enters UNMULTIPLIED via Cbm0.
    u64 X1b = pk(x1, x1), X2b = pk(x2, x2);
    u64 H1b = pk(h1, h1), H2b = pk(h2, h2);
    u64 qa  = fma2(X2b, c.A_x2, c.Bm12);
    qa      = fma2(X1b, c.A_x1, qa);
    u64 qb  = fma2(H1b, c.A_h1, mul2(H2b, c.A_h2));
    u64 Q12 = add2(qa, qb);                               // (q1, q2)
    u64 Q34 = fma2(H1b, c.A3_h1, fma2(H2b, c.A3_h2, c.Bm34)); // (q3, q4)
    u64 PP  = fma2(Hh, Q34, fma2(X, Q12, c.Cbm0));        // bm0 added here
    float plo, phi_; upk(plo, phi_, PP);
    float phi = plo + phi_;

    float t = FIRST ? 1.0f : tanh_approx(phi);   // delta = 0.5 + 0.5 t

    if (ADDSC) {
        accQ2 = fma2(X, X, accQ2);               // packed  sum x^2
        float kx = fmaf(200.0f, g, kuh);         // u_s = K · x  (exact)
        accR = fmaf(kx, kx, accR);
        accT += t;                               // sum delta via 0.5 t fold
    }

    // ---- advance (2 packed FMAs) ----
    u64 T2 = pk(t, t);
    u64 G2 = pk(g, g);
    X  = fma2(T2, G2, BX);
    Hh = fma2(T2, DH, HM);
}

__global__ void __launch_bounds__(64, 1) cstr_traj_kernel(
    const float* __restrict__ w,   // (B, 2, T)
    const float* __restrict__ K,   // (1, 2)
    const float* __restrict__ L,   // (4, 4)
    const float* __restrict__ M,   // (1, 4)
    const float* __restrict__ Mo,  // (1, 1)
    float* __restrict__ out)       // (B,)
{
    int b = blockIdx.x * blockDim.x + threadIdx.x;

    const float s = 0.5f;  // sigmoid(phi) = 0.5 + 0.5*tanh(0.5*phi)
    float K1 = __ldg(K), K2 = __ldg(K + 1);
    float l[16];
#pragma unroll
    for (int i = 0; i < 16; i++) l[i] = __ldg(L + i);
    float a11 = s * l[0],           a22 = s * l[5];
    float a33 = s * l[10],          a44 = s * l[15];
    float a12 = s * (l[1] + l[4]),  a13 = s * (l[2] + l[8]);
    float a14 = s * (l[3] + l[12]), a23 = s * (l[6] + l[9]);
    float a24 = s * (l[7] + l[13]), a34 = s * (l[11] + l[14]);
    float bm1 = s * __ldg(M),       bm2 = s * __ldg(M + 1);
    float bm3 = s * __ldg(M + 2),   bm4 = s * __ldg(M + 3);
    float bm0 = s * __ldg(Mo);

    CP c;
    c.K1 = K1; c.K2 = K2;
    c.q1 = 0.005f * K1; c.q2 = 0.005f * K2;
    c.NEG1 = pk(-1.0f, -1.0f);
    c.HALF = pk(0.5f, 0.5f);
    c.E2   = pk(1.0f - 2.0f * HH, 1.0f - 2.0f * HH);   // 0.98
    c.HH2  = pk(HH, HH);
    c.Cp   = pk(0.5f * HH * HH, -HH * HH);             // (+h^2/2, -h^2)
    c.A_x1  = pk(a11, 0.0f);
    c.A_x2  = pk(a12, a22);
    c.A_h1  = pk(a13, a23);
    c.A_h2  = pk(a14, a24);
    c.Bm12  = pk(bm1, bm2);
    c.A3_h1 = pk(a33, 0.0f);
    c.A3_h2 = pk(a34, a44);
    c.Bm34  = pk(bm3, bm4);         // FIXED: bm0 no longer folded here
    c.Cbm0  = pk(bm0, 0.0f);        // bm0 enters unmultiplied

    const float4* w0 = (const float4*)(w + (size_t)b * 2 * TSTEPS);
    const float4* w1 = (const float4*)(w + (size_t)b * 2 * TSTEPS + TSTEPS);

    u64 X  = pk(1.0f, 0.0f);
    u64 Hh = pk(1.0f, 0.0f);
    u64 accQ2 = pk(0.0f, 0.0f);
    float accR = 0.0f, accT = 0.0f;

    // ---- software prefetch pipeline: PD groups in registers ----
    float4 bA[PD], bB[PD];
#pragma unroll
    for (int d = 0; d < PD; ++d) { bA[d] = w0[d]; bB[d] = w1[d]; }

    // Group 0: step 0 is FIRST (delta forced to 1; dx=0 makes t inert)
    {
        float4 wa = bA[0], wb = bB[0];
        bA[0] = w0[PD]; bB[0] = w1[PD];
        stepP<true,  true>(c, wa.x, wb.x, X, Hh, accQ2, accR, accT);
        stepP<false, true>(c, wa.y, wb.y, X, Hh, accQ2, accR, accT);
        stepP<false, true>(c, wa.z, wb.z, X, Hh, accQ2, accR, accT);
        stepP<false, true>(c, wa.w, wb.w, X, Hh, accQ2, accR, accT);
    }
#pragma unroll
    for (int d = 1; d < PD; ++d) {
        float4 wa = bA[d], wb = bB[d];
        bA[d] = w0[PD + d]; bB[d] = w1[PD + d];
        stepP<false, true>(c, wa.x, wb.x, X, Hh, accQ2, accR, accT);
        stepP<false, true>(c, wa.y, wb.y, X, Hh, accQ2, accR, accT);
        stepP<false, true>(c, wa.z, wb.z, X, Hh, accQ2, accR, accT);
        stepP<false, true>(c, wa.w, wb.w, X, Hh, accQ2, accR, accT);
    }

    // Main: base = PD, 2PD, ...; consume slot d = group base+d, prefetch +PD.
    for (int base = PD; base < NG - PD; base += PD) {
#pragma unroll
        for (int d = 0; d < PD; ++d) {
            float4 wa = bA[d], wb = bB[d];
            bA[d] = w0[base + PD + d];
            bB[d] = w1[base + PD + d];
            stepP<false, true>(c, wa.x, wb.x, X, Hh, accQ2, accR, accT);
            stepP<false, true>(c, wa.y, wb.y, X, Hh, accQ2, accR, accT);
            stepP<false, true>(c, wa.z, wb.z, X, Hh, accQ2, accR, accT);
            stepP<false, true>(c, wa.w, wb.w, X, Hh, accQ2, accR, accT);
        }
    }

    // Tail: groups NG-PD .. NG-1 from the buffers (static slots)
#pragma unroll
    for (int d = 0; d < PD - 1; ++d) {
        float4 wa = bA[d], wb = bB[d];
        stepP<false, true>(c, wa.x, wb.x, X, Hh, accQ2, accR, accT);
        stepP<false, true>(c, wa.y, wb.y, X, Hh, accQ2, accR, accT);
        stepP<false, true>(c, wa.z, wb.z, X, Hh, accQ2, accR, accT);
        stepP<false, true>(c, wa.w, wb.w, X, Hh, accQ2, accR, accT);
    }
    {   // last group: final step (i = T-1) updates state, adds no stage cost
        float4 wa = bA[PD - 1], wb = bB[PD - 1];
        stepP<false, true >(c, wa.x, wb.x, X, Hh, accQ2, accR, accT);
        stepP<false, true >(c, wa.y, wb.y, X, Hh, accQ2, accR, accT);
        stepP<false, true >(c, wa.z, wb.z, X, Hh, accQ2, accR, accT);
        stepP<false, false>(c, wa.w, wb.w, X, Hh, accQ2, accR, accT);
    }

    // J = sum x^Tx + 0.1 sum u_s^2 + [2047*0.5 + 0.5 sum t] + 10*|x_T|^2
    float aq1, aq2; upk(aq1, aq2, accQ2);
    float J = aq1 + aq2;
    J = fmaf(0.1f, accR, J);
    J = fmaf(0.5f, accT, J);
    J = J + 1023.0f;          // 2047*0.5 ; step0's t=1 contributes the extra 0.5
    float x1, x2; upk(x1, x2, X);
    J = fmaf(10.0f * x1, x1, J);
    J = fmaf(10.0f * x2, x2, J);

    if (b < BSIZE) out[b] = J;
}

extern "C" void kernel_launch(void* const* d_in, const int* in_sizes, int n_in,
                              void* d_out, int out_size)
{
    const float* w  = (const float*)d_in[0];
    const float* K  = (const float*)d_in[1];
    const float* L  = (const float*)d_in[2];
    const float* M  = (const float*)d_in[3];
    const float* Mo = (const float*)d_in[4];
    float* out = (float*)d_out;

    cstr_traj_kernel<<<BSIZE / 64, 64>>>(w, K, L, M, Mo, out);
}

// round 9
// speedup vs baseline: 1.1904x; 1.1014x over previous
#include <cuda_runtime.h>

#define TSTEPS 2048
#define BSIZE  8192
#define HH     0.01f
#define NG     (TSTEPS / 4)   // 512 groups of 4 steps
#define PD     4              // prefetch distance (groups)

__device__ __forceinline__ float tanh_approx(float x) {
    float y; asm("tanh.approx.f32 %0, %1;" : "=f"(y) : "f"(x)); return y;
}

struct Consts {
    float a11, a12, a13, a14, a22, a23, a24, a33, a34, a44;  // 0.5 * symmetrized L
    float bm1, bm2, bm3, bm4, bm0;                           // 0.5 * M, 0.5 * Mo
    float K1, K2;
};

// One step, delta-form, op-minimized (~37 fma-pipe ops).
// sigmoid(phi) = 0.5 + 0.5*tanh(phi/2); the 1/2 is folded into a/bm coeffs.
template<bool FIRST, bool ADDSC>
__device__ __forceinline__ void step(const Consts& c, float w1, float w2,
                                     float& x1, float& x2, float& h1, float& h2,
                                     float& accQ, float& accR, float& accT)
{
    const float E11 = 1.0f - 2.0f * HH;   // 0.98
    const float C1  = 0.5f * HH * HH;     // +h^2/2 (collapsed RK4, x1 eq)
    const float C2  = -HH * HH;           // -h^2   (x2 eq)

    float delta;
    if (FIRST) {
        delta = 1.0f;   // reference forces delta=1 at i==0 (dx==0 anyway)
    } else {
        // phi tree: 14 ops, depth-ordered so phi is ready at ~20 cyc
        float q4 = fmaf(c.a44, h2, c.bm4);
        float q3 = fmaf(c.a33, h1, fmaf(c.a34, h2, c.bm3));
        float q2 = fmaf(c.a22, x2, fmaf(c.a23, h1, fmaf(c.a24, h2, c.bm2)));
        float q1 = fmaf(c.a11, x1, fmaf(c.a12, x2,
                   fmaf(c.a13, h1, fmaf(c.a14, h2, c.bm1))));
        float r  = fmaf(h2, q4, c.bm0);   // shallow terms first
        r        = fmaf(h1, q3, r);
        r        = fmaf(x2, q2, r);
        float phi = fmaf(x1, q1, r);
        float t = tanh_approx(phi);
        delta = fmaf(0.5f, t, 0.5f);
    }

    // hoisted (issues under the tanh shadow on adjacent steps)
    float dx1 = x1 - h1, dx2 = x2 - h2;
    float kuh = fmaf(c.K2, h2, c.K1 * h1);    // K · x_hat
    float kdx = fmaf(c.K2, dx2, c.K1 * dx1);  // K · (x - x_hat)
    float b1 = fmaf(E11, x1, fmaf(HH, x2, w1 + C1));
    float b2 = fmaf(HH,  x1, fmaf(E11, x2, w2 + C2));

    if (ADDSC) {
        float kx = kuh + kdx;                 // u_s = K · x
        accQ = fmaf(x1, x1, accQ);
        accQ = fmaf(x2, x2, accQ);
        accR = fmaf(kx, kx, accR);            // 0.1 applied once at the end
        accT = accT + delta;                  // LAM * delta, LAM = 1
    }

    float u = fmaf(delta, kdx, kuh);          // K · x_hat_new
    x1 = fmaf(HH, u, b1);
    x2 = fmaf(HH, u, b2);
    h1 = fmaf(delta, dx1, h1);
    h2 = fmaf(delta, dx2, h2);
}

__global__ void __launch_bounds__(64, 1) cstr_traj_kernel(
    const float* __restrict__ w,   // (B, 2, T)
    const float* __restrict__ K,   // (1, 2)
    const float* __restrict__ L,   // (4, 4)
    const float* __restrict__ M,   // (1, 4)
    const float* __restrict__ Mo,  // (1, 1)
    float* __restrict__ out)       // (B,)
{
    int b = blockIdx.x * blockDim.x + threadIdx.x;

    const float s = 0.5f;  // sigmoid(phi) = 0.5 + 0.5*tanh(0.5*phi)
    Consts c;
    c.K1 = __ldg(K);  c.K2 = __ldg(K + 1);
    float l[16];
#pragma unroll
    for (int i = 0; i < 16; i++) l[i] = __ldg(L + i);
    c.a11 = s * l[0];           c.a22 = s * l[5];
    c.a33 = s * l[10];          c.a44 = s * l[15];
    c.a12 = s * (l[1] + l[4]);  c.a13 = s * (l[2] + l[8]);
    c.a14 = s * (l[3] + l[12]); c.a23 = s * (l[6] + l[9]);
    c.a24 = s * (l[7] + l[13]); c.a34 = s * (l[11] + l[14]);
    c.bm1 = s * __ldg(M);       c.bm2 = s * __ldg(M + 1);
    c.bm3 = s * __ldg(M + 2);   c.bm4 = s * __ldg(M + 3);
    c.bm0 = s * __ldg(Mo);

    const float4* w0 = (const float4*)(w + (size_t)b * 2 * TSTEPS);
    const float4* w1 = (const float4*)(w + (size_t)b * 2 * TSTEPS + TSTEPS);

    float x1 = 1.0f, x2 = 0.0f, h1 = 1.0f, h2 = 0.0f;
    float accQ = 0.0f, accR = 0.0f, accT = 0.0f;

    // ---- software prefetch pipeline: PD groups in registers ----
    float4 bA[PD], bB[PD];
#pragma unroll
    for (int d = 0; d < PD; ++d) { bA[d] = w0[d]; bB[d] = w1[d]; }

    // Group 0: step 0 is FIRST (delta forced to 1)
    {
        float4 wa = bA[0], wb = bB[0];
        bA[0] = w0[PD]; bB[0] = w1[PD];
        step<true,  true>(c, wa.x, wb.x, x1, x2, h1, h2, accQ, accR, accT);
        step<false, true>(c, wa.y, wb.y, x1, x2, h1, h2, accQ, accR, accT);
        step<false, true>(c, wa.z, wb.z, x1, x2, h1, h2, accQ, accR, accT);
        step<false, true>(c, wa.w, wb.w, x1, x2, h1, h2, accQ, accR, accT);
    }
#pragma unroll
    for (int d = 1; d < PD; ++d) {
        float4 wa = bA[d], wb = bB[d];
        bA[d] = w0[PD + d]; bB[d] = w1[PD + d];
        step<false, true>(c, wa.x, wb.x, x1, x2, h1, h2, accQ, accR, accT);
        step<false, true>(c, wa.y, wb.y, x1, x2, h1, h2, accQ, accR, accT);
        step<false, true>(c, wa.z, wb.z, x1, x2, h1, h2, accQ, accR, accT);
        step<false, true>(c, wa.w, wb.w, x1, x2, h1, h2, accQ, accR, accT);
    }

    // Main: consume slot d = group base+d, prefetch group base+PD+d
    for (int base = PD; base < NG - PD; base += PD) {
#pragma unroll
        for (int d = 0; d < PD; ++d) {
            float4 wa = bA[d], wb = bB[d];
            bA[d] = w0[base + PD + d];
            bB[d] = w1[base + PD + d];
            step<false, true>(c, wa.x, wb.x, x1, x2, h1, h2, accQ, accR, accT);
            step<false, true>(c, wa.y, wb.y, x1, x2, h1, h2, accQ, accR, accT);
            step<false, true>(c, wa.z, wb.z, x1, x2, h1, h2, accQ, accR, accT);
            step<false, true>(c, wa.w, wb.w, x1, x2, h1, h2, accQ, accR, accT);
        }
    }

    // Tail: groups NG-PD .. NG-1 from the buffers (static slots)
#pragma unroll
    for (int d = 0; d < PD - 1; ++d) {
        float4 wa = bA[d], wb = bB[d];
        step<false, true>(c, wa.x, wb.x, x1, x2, h1, h2, accQ, accR, accT);
        step<false, true>(c, wa.y, wb.y, x1, x2, h1, h2, accQ, accR, accT);
        step<false, true>(c, wa.z, wb.z, x1, x2, h1, h2, accQ, accR, accT);
        step<false, true>(c, wa.w, wb.w, x1, x2, h1, h2, accQ, accR, accT);
    }
    {   // last group: final step (i = T-1) updates state, adds no stage cost
        float4 wa = bA[PD - 1], wb = bB[PD - 1];
        step<false, true >(c, wa.x, wb.x, x1, x2, h1, h2, accQ, accR, accT);
        step<false, true >(c, wa.y, wb.y, x1, x2, h1, h2, accQ, accR, accT);
        step<false, true >(c, wa.z, wb.z, x1, x2, h1, h2, accQ, accR, accT);
        step<false, false>(c, wa.w, wb.w, x1, x2, h1, h2, accQ, accR, accT);
    }

    // J = sum x^T x + 0.1 * sum u_s^2 + sum delta + terminal 10*|x_T|^2
    float J = accQ;
    J = fmaf(0.1f, accR, J);
    J = J + accT;
    J = fmaf(10.0f * x1, x1, J);
    J = fmaf(10.0f * x2, x2, J);

    if (b < BSIZE) out[b] = J;
}

extern "C" void kernel_launch(void* const* d_in, const int* in_sizes, int n_in,
                              void* d_out, int out_size)
{
    const float* w  = (const float*)d_in[0];
    const float* K  = (const float*)d_in[1];
    const float* L  = (const float*)d_in[2];
    const float* M  = (const float*)d_in[3];
    const float* Mo = (const float*)d_in[4];
    float* out = (float*)d_out;

    // 8192 trajectories, 1 thread each; 128 blocks x 64 threads = 256 warps,
    // one warp per SMSP (single-warp FMA-throughput regime).
    cstr_traj_kernel<<<BSIZE / 64, 64>>>(w, K, L, M, Mo, out);
}

// round 10
// speedup vs baseline: 1.1999x; 1.0080x over previous
#include <cuda_runtime.h>

#define TSTEPS 2048
#define BSIZE  8192
#define HH     0.01f
#define NG     (TSTEPS / 4)   // 512 groups of 4 steps
#define PD     4              // prefetch distance (groups)

__device__ __forceinline__ float tanh_approx(float x) {
    float y; asm("tanh.approx.f32 %0, %1;" : "=f"(y) : "f"(x)); return y;
}

struct Consts {
    float a11, a12, a13, a14, a22, a23, a24, a33, a34, a44;  // 0.5 * symmetrized L
    float bm1, bm2, bm3, bm4, bm0;                           // 0.5 * M, 0.5 * Mo
    float K1, K2;
};

// One step, t-form: delta/u folded out of all chains.
//   delta = 0.5 + 0.5 t  (t = tanh(phi/2); the 1/2 lives in the a/bm coeffs)
//   x' = bx + t*g,  h' = hm + t*dh,  stage-Sigma delta recovered at the end.
// phi for the NEXT step is computed at the tail (loop-carried).
// Chain: tanh(60) -> state fma(4) -> tree(24) -> next tanh. F ~= 43 fma-ops.
template<bool ADDSC>
__device__ __forceinline__ void step(const Consts& c, float w1, float w2,
                                     float& x1, float& x2, float& h1, float& h2,
                                     float& phi, float& accQ, float& accR,
                                     float& accT)
{
    const float E11 = 1.0f - 2.0f * HH;   // 0.98
    const float C1  = 0.5f * HH * HH;     // +h^2/2 (collapsed RK4, x1 eq)
    const float C2  = -HH * HH;           // -h^2   (x2 eq)

    float t = tanh_approx(phi);           // the ONLY long-latency op on the chain

    // ---- geometry: all pre-t, issues under the tanh shadow ----
    float dx1 = x1 - h1, dx2 = x2 - h2;
    float kuh = fmaf(c.K2, h2, c.K1 * h1);     // K · x_hat
    float kdx = fmaf(c.K2, dx2, c.K1 * dx1);   // K · (x - x_hat)
    float g   = 0.005f * kdx;                  // t-coefficient of x'
    float bb  = fmaf(HH, kuh, g);              // HH*(K·xh + 0.5 K·dx)
    float b1  = fmaf(E11, x1, fmaf(HH, x2, w1 + C1));
    float b2  = fmaf(HH,  x1, fmaf(E11, x2, w2 + C2));
    float bx1 = b1 + bb, bx2 = b2 + bb;
    float dh1 = 0.5f * dx1, dh2 = 0.5f * dx2;
    float hm1 = h1 + dh1,   hm2 = h2 + dh2;

    if (ADDSC) {
        float kx = kuh + kdx;                  // u_s = K · x (exact)
        accQ = fmaf(x1, x1, accQ);
        accQ = fmaf(x2, x2, accQ);
        accR = fmaf(kx, kx, accR);             // 0.1 applied once at the end
        accT = accT + t;                       // Sigma delta = 0.5*N + 0.5*Sigma t
    }

    // ---- post-tanh: one FMA per state variable ----
    x1 = fmaf(t, g,   bx1);
    x2 = fmaf(t, g,   bx2);
    h1 = fmaf(t, dh1, hm1);
    h2 = fmaf(t, dh2, hm2);

    // ---- phi tree for the NEXT step (14 fma, depth 24 from new state) ----
    float q4 = fmaf(c.a44, h2, c.bm4);
    float q3 = fmaf(c.a33, h1, fmaf(c.a34, h2, c.bm3));
    float q2 = fmaf(c.a22, x2, fmaf(c.a23, h1, fmaf(c.a24, h2, c.bm2)));
    float q1 = fmaf(c.a11, x1, fmaf(c.a12, x2,
               fmaf(c.a13, h1, fmaf(c.a14, h2, c.bm1))));
    float r  = fmaf(h2, q4, c.bm0);
    r        = fmaf(h1, q3, r);
    r        = fmaf(x2, q2, r);
    phi      = fmaf(x1, q1, r);
}

__global__ void __launch_bounds__(64, 1) cstr_traj_kernel(
    const float* __restrict__ w,   // (B, 2, T)
    const float* __restrict__ K,   // (1, 2)
    const float* __restrict__ L,   // (4, 4)
    const float* __restrict__ M,   // (1, 4)
    const float* __restrict__ Mo,  // (1, 1)
    float* __restrict__ out)       // (B,)
{
    int b = blockIdx.x * blockDim.x + threadIdx.x;

    const float s = 0.5f;  // sigmoid(phi) = 0.5 + 0.5*tanh(0.5*phi)
    Consts c;
    c.K1 = __ldg(K);  c.K2 = __ldg(K + 1);
    float l[16];
#pragma unroll
    for (int i = 0; i < 16; i++) l[i] = __ldg(L + i);
    c.a11 = s * l[0];           c.a22 = s * l[5];
    c.a33 = s * l[10];          c.a44 = s * l[15];
    c.a12 = s * (l[1] + l[4]);  c.a13 = s * (l[2] + l[8]);
    c.a14 = s * (l[3] + l[12]); c.a23 = s * (l[6] + l[9]);
    c.a24 = s * (l[7] + l[13]); c.a34 = s * (l[11] + l[14]);
    c.bm1 = s * __ldg(M);       c.bm2 = s * __ldg(M + 1);
    c.bm3 = s * __ldg(M + 2);   c.bm4 = s * __ldg(M + 3);
    c.bm0 = s * __ldg(Mo);

    const float4* w0 = (const float4*)(w + (size_t)b * 2 * TSTEPS);
    const float4* w1 = (const float4*)(w + (size_t)b * 2 * TSTEPS + TSTEPS);

    float x1 = 1.0f, x2 = 0.0f, h1 = 1.0f, h2 = 0.0f;
    float accQ = 0.0f, accR = 0.0f, accT = 0.0f;
    // Step 0: reference forces delta=1 with x_hat frozen. dx==0 makes t inert
    // in the dynamics; phi=+30 saturates tanh to exactly 1.0 so delta=1 in the
    // stage cost too. No special-cased step needed.
    float phi = 30.0f;

    // ---- software prefetch pipeline: PD groups in registers ----
    float4 bA[PD], bB[PD];
#pragma unroll
    for (int d = 0; d < PD; ++d) { bA[d] = w0[d]; bB[d] = w1[d]; }

    // First PD groups (consume slot d, prefetch group PD+d)
#pragma unroll
    for (int d = 0; d < PD; ++d) {
        float4 wa = bA[d], wb = bB[d];
        bA[d] = w0[PD + d]; bB[d] = w1[PD + d];
        step<true>(c, wa.x, wb.x, x1, x2, h1, h2, phi, accQ, accR, accT);
        step<true>(c, wa.y, wb.y, x1, x2, h1, h2, phi, accQ, accR, accT);
        step<true>(c, wa.z, wb.z, x1, x2, h1, h2, phi, accQ, accR, accT);
        step<true>(c, wa.w, wb.w, x1, x2, h1, h2, phi, accQ, accR, accT);
    }

    // Main: consume slot d = group base+d, prefetch group base+PD+d
    for (int base = PD; base < NG - PD; base += PD) {
#pragma unroll
        for (int d = 0; d < PD; ++d) {
            float4 wa = bA[d], wb = bB[d];
            bA[d] = w0[base + PD + d];
            bB[d] = w1[base + PD + d];
            step<true>(c, wa.x, wb.x, x1, x2, h1, h2, phi, accQ, accR, accT);
            step<true>(c, wa.y, wb.y, x1, x2, h1, h2, phi, accQ, accR, accT);
            step<true>(c, wa.z, wb.z, x1, x2, h1, h2, phi, accQ, accR, accT);
            step<true>(c, wa.w, wb.w, x1, x2, h1, h2, phi, accQ, accR, accT);
        }
    }

    // Tail: groups NG-PD .. NG-1 from the buffers (static slots)
#pragma unroll
    for (int d = 0; d < PD - 1; ++d) {
        float4 wa = bA[d], wb = bB[d];
        step<true>(c, wa.x, wb.x, x1, x2, h1, h2, phi, accQ, accR, accT);
        step<true>(c, wa.y, wb.y, x1, x2, h1, h2, phi, accQ, accR, accT);
        step<true>(c, wa.z, wb.z, x1, x2, h1, h2, phi, accQ, accR, accT);
        step<true>(c, wa.w, wb.w, x1, x2, h1, h2, phi, accQ, accR, accT);
    }
    {   // last group: final step (i = T-1) updates state, adds no stage cost
        float4 wa = bA[PD - 1], wb = bB[PD - 1];
        step<true >(c, wa.x, wb.x, x1, x2, h1, h2, phi, accQ, accR, accT);
        step<true >(c, wa.y, wb.y, x1, x2, h1, h2, phi, accQ, accR, accT);
        step<true >(c, wa.z, wb.z, x1, x2, h1, h2, phi, accQ, accR, accT);
        step<false>(c, wa.w, wb.w, x1, x2, h1, h2, phi, accQ, accR, accT);
    }

    // J = Sigma x^T x + 0.1 Sigma u_s^2 + [2047*0.5 + 0.5 Sigma t] + 10|x_T|^2
    float J = accQ;
    J = fmaf(0.1f, accR, J);
    J = fmaf(0.5f, accT, J);
    J = J + 1023.5f;
    J = fmaf(10.0f * x1, x1, J);
    J = fmaf(10.0f * x2, x2, J);

    if (b < BSIZE) out[b] = J;
}

extern "C" void kernel_launch(void* const* d_in, const int* in_sizes, int n_in,
                              void* d_out, int out_size)
{
    const float* w  = (const float*)d_in[0];
    const float* K  = (const float*)d_in[1];
    const float* L  = (const float*)d_in[2];
    const float* M  = (const float*)d_in[3];
    const float* Mo = (const float*)d_in[4];
    float* out = (float*)d_out;

    // 8192 trajectories, 1 thread each; 128 blocks x 64 threads = 256 warps,
    // one warp per SMSP.
    cstr_traj_kernel<<<BSIZE / 64, 64>>>(w, K, L, M, Mo, out);
}

// round 11
// speedup vs baseline: 1.2693x; 1.0579x over previous
#include <cuda_runtime.h>

#define TSTEPS 2048
#define BSIZE  8192
#define HH     0.01f
#define NG     (TSTEPS / 4)   // 512 groups of 4 steps
#define PD     4              // prefetch distance (groups)

__device__ __forceinline__ float ex2f(float x) {
    float y; asm("ex2.approx.ftz.f32 %0, %1;" : "=f"(y) : "f"(x)); return y;
}
__device__ __forceinline__ float rcpf(float x) {
    float y; asm("rcp.approx.ftz.f32 %0, %1;" : "=f"(y) : "f"(x)); return y;
}

struct Consts {
    float a11, a12, a13, a14, a22, a23, a24, a33, a34, a44;  // -log2e * symm L
    float bm1, bm2, bm3, bm4, bm0;                           // -log2e * M, Mo
    float K1, K2;
};

// One step. delta = sigmoid(phi) = rcp(1 + ex2(phiS)), phiS = -log2(e)*phi
// loop-carried (computed from the NEW state at the tail of each step).
// Chain: ex2(16) -> +1 (4) -> rcp(16) -> state fma(4) -> tree(~20) = ~60 cyc.
// Everything else issues inside the MUFU shadows.
template<bool ADDSC>
__device__ __forceinline__ void step(const Consts& c, float w1, float w2,
                                     float& x1, float& x2, float& h1, float& h2,
                                     float& phiS, float& accQ, float& accR,
                                     float& accT)
{
    const float E11 = 1.0f - 2.0f * HH;   // 0.98
    const float C1  = 0.5f * HH * HH;     // +h^2/2 (collapsed RK4, x1 eq)
    const float C2  = -HH * HH;           // -h^2   (x2 eq)

    float e = ex2f(phiS);                 // MUFU #1 (issues at step start)

    // ---- hoisted geometry/cost: fills the ex2 + rcp shadows ----
    float dx1 = x1 - h1, dx2 = x2 - h2;
    float kuh = fmaf(c.K2, h2, c.K1 * h1);     // K · x_hat
    float kdx = fmaf(c.K2, dx2, c.K1 * dx1);   // K · (x - x_hat)
    float hkdx = HH * kdx;                     // delta-coefficient of x'
    float b1  = fmaf(E11, x1, fmaf(HH, x2, w1 + C1));
    float b2  = fmaf(HH,  x1, fmaf(E11, x2, w2 + C2));
    float bu1 = fmaf(HH, kuh, b1);
    float bu2 = fmaf(HH, kuh, b2);

    if (ADDSC) {
        float kx = kuh + kdx;                  // u_s = K · x (exact)
        accQ = fmaf(x1, x1, accQ);
        accQ = fmaf(x2, x2, accQ);
        accR = fmaf(kx, kx, accR);             // 0.1 applied once at the end
    }

    float den   = 1.0f + e;                    // FADD on the chain
    float delta = rcpf(den);                   // MUFU #2

    if (ADDSC) accT = accT + delta;            // LAM * delta, off the chain

    // ---- post-rcp: one FMA per state variable ----
    x1 = fmaf(delta, hkdx, bu1);               // b + HH*(kuh + delta*kdx)
    x2 = fmaf(delta, hkdx, bu2);
    h1 = fmaf(delta, dx1, h1);
    h2 = fmaf(delta, dx2, h2);

    // ---- phiS for the NEXT step (14 fma, depth ~20 from new state) ----
    float q4 = fmaf(c.a44, h2, c.bm4);
    float q3 = fmaf(c.a33, h1, fmaf(c.a34, h2, c.bm3));
    float q2 = fmaf(c.a22, x2, fmaf(c.a23, h1, fmaf(c.a24, h2, c.bm2)));
    float q1 = fmaf(c.a11, x1, fmaf(c.a12, x2,
               fmaf(c.a13, h1, fmaf(c.a14, h2, c.bm1))));
    float r  = fmaf(h2, q4, c.bm0);            // shallow q's consumed first
    r        = fmaf(h1, q3, r);
    r        = fmaf(x2, q2, r);
    phiS     = fmaf(x1, q1, r);
}

__global__ void __launch_bounds__(64, 1) cstr_traj_kernel(
    const float* __restrict__ w,   // (B, 2, T)
    const float* __restrict__ K,   // (1, 2)
    const float* __restrict__ L,   // (4, 4)
    const float* __restrict__ M,   // (1, 4)
    const float* __restrict__ Mo,  // (1, 1)
    float* __restrict__ out)       // (B,)
{
    int b = blockIdx.x * blockDim.x + threadIdx.x;

    const float s = -1.44269504088896340736f;  // -log2(e), folded into phi
    Consts c;
    c.K1 = __ldg(K);  c.K2 = __ldg(K + 1);
    float l[16];
#pragma unroll
    for (int i = 0; i < 16; i++) l[i] = __ldg(L + i);
    c.a11 = s * l[0];           c.a22 = s * l[5];
    c.a33 = s * l[10];          c.a44 = s * l[15];
    c.a12 = s * (l[1] + l[4]);  c.a13 = s * (l[2] + l[8]);
    c.a14 = s * (l[3] + l[12]); c.a23 = s * (l[6] + l[9]);
    c.a24 = s * (l[7] + l[13]); c.a34 = s * (l[11] + l[14]);
    c.bm1 = s * __ldg(M);       c.bm2 = s * __ldg(M + 1);
    c.bm3 = s * __ldg(M + 2);   c.bm4 = s * __ldg(M + 3);
    c.bm0 = s * __ldg(Mo);

    const float4* w0 = (const float4*)(w + (size_t)b * 2 * TSTEPS);
    const float4* w1 = (const float4*)(w + (size_t)b * 2 * TSTEPS + TSTEPS);

    float x1 = 1.0f, x2 = 0.0f, h1 = 1.0f, h2 = 0.0f;
    float accQ = 0.0f, accR = 0.0f, accT = 0.0f;
    // Step 0: reference forces delta=1 with x_hat frozen. dx==0 makes delta
    // inert in the dynamics; phiS=-200 -> ex2 flushes to 0 -> delta = rcp(1)
    // = exactly 1.0, so the stage cost is exact too. No special-cased step.
    float phiS = -200.0f;

    // ---- software prefetch pipeline: PD groups in registers ----
    float4 bA[PD], bB[PD];
#pragma unroll
    for (int d = 0; d < PD; ++d) { bA[d] = w0[d]; bB[d] = w1[d]; }

    // First PD groups (consume slot d, prefetch group PD+d)
#pragma unroll
    for (int d = 0; d < PD; ++d) {
        float4 wa = bA[d], wb = bB[d];
        bA[d] = w0[PD + d]; bB[d] = w1[PD + d];
        step<true>(c, wa.x, wb.x, x1, x2, h1, h2, phiS, accQ, accR, accT);
        step<true>(c, wa.y, wb.y, x1, x2, h1, h2, phiS, accQ, accR, accT);
        step<true>(c, wa.z, wb.z, x1, x2, h1, h2, phiS, accQ, accR, accT);
        step<true>(c, wa.w, wb.w, x1, x2, h1, h2, phiS, accQ, accR, accT);
    }

    // Main: consume slot d = group base+d, prefetch group base+PD+d
    for (int base = PD; base < NG - PD; base += PD) {
#pragma unroll
        for (int d = 0; d < PD; ++d) {
            float4 wa = bA[d], wb = bB[d];
            bA[d] = w0[base + PD + d];
            bB[d] = w1[base + PD + d];
            step<true>(c, wa.x, wb.x, x1, x2, h1, h2, phiS, accQ, accR, accT);
            step<true>(c, wa.y, wb.y, x1, x2, h1, h2, phiS, accQ, accR, accT);
            step<true>(c, wa.z, wb.z, x1, x2, h1, h2, phiS, accQ, accR, accT);
            step<true>(c, wa.w, wb.w, x1, x2, h1, h2, phiS, accQ, accR, accT);
        }
    }

    // Tail: groups NG-PD .. NG-1 from the buffers (static slots)
#pragma unroll
    for (int d = 0; d < PD - 1; ++d) {
        float4 wa = bA[d], wb = bB[d];
        step<true>(c, wa.x, wb.x, x1, x2, h1, h2, phiS, accQ, accR, accT);
        step<true>(c, wa.y, wb.y, x1, x2, h1, h2, phiS, accQ, accR, accT);
        step<true>(c, wa.z, wb.z, x1, x2, h1, h2, phiS, accQ, accR, accT);
        step<true>(c, wa.w, wb.w, x1, x2, h1, h2, phiS, accQ, accR, accT);
    }
    {   // last group: final step (i = T-1) updates state, adds no stage cost
        float4 wa = bA[PD - 1], wb = bB[PD - 1];
        step<true >(c, wa.x, wb.x, x1, x2, h1, h2, phiS, accQ, accR, accT);
        step<true >(c, wa.y, wb.y, x1, x2, h1, h2, phiS, accQ, accR, accT);
        step<true >(c, wa.z, wb.z, x1, x2, h1, h2, phiS, accQ, accR, accT);
        step<false>(c, wa.w, wb.w, x1, x2, h1, h2, phiS, accQ, accR, accT);
    }

    // J = Sigma x^T x + 0.1 Sigma u_s^2 + Sigma delta + terminal 10|x_T|^2
    float J = accQ;
    J = fmaf(0.1f, accR, J);
    J = J + accT;
    J = fmaf(10.0f * x1, x1, J);
    J = fmaf(10.0f * x2, x2, J);

    if (b < BSIZE) out[b] = J;
}

extern "C" void kernel_launch(void* const* d_in, const int* in_sizes, int n_in,
                              void* d_out, int out_size)
{
    const float* w  = (const float*)d_in[0];
    const float* K  = (const float*)d_in[1];
    const float* L  = (const float*)d_in[2];
    const float* M  = (const float*)d_in[3];
    const float* Mo = (const float*)d_in[4];
    float* out = (float*)d_out;

    // 8192 trajectories, 1 thread each; 128 blocks x 64 threads = 256 warps,
    // one warp per SMSP.
    cstr_traj_kernel<<<BSIZE / 64, 64>>>(w, K, L, M, Mo, out);
}

// round 12
// speedup vs baseline: 1.3591x; 1.0707x over previous
#include <cuda_runtime.h>

#define TSTEPS 2048
#define BSIZE  8192
#define HH     0.01f
#define NG     (TSTEPS / 4)   // 512 groups of 4 steps
#define PD     4              // prefetch distance (groups)

typedef unsigned long long u64;

__device__ __forceinline__ float ex2f(float x) {
    float y; asm("ex2.approx.ftz.f32 %0, %1;" : "=f"(y) : "f"(x)); return y;
}
__device__ __forceinline__ float rcpf(float x) {
    float y; asm("rcp.approx.ftz.f32 %0, %1;" : "=f"(y) : "f"(x)); return y;
}
__device__ __forceinline__ u64 pk(float lo, float hi) {
    u64 r; asm("mov.b64 %0, {%1, %2};" : "=l"(r) : "f"(lo), "f"(hi)); return r;
}
__device__ __forceinline__ void upk(float& lo, float& hi, u64 v) {
    asm("mov.b64 {%0, %1}, %2;" : "=f"(lo), "=f"(hi) : "l"(v));
}
__device__ __forceinline__ u64 fma2(u64 a, u64 b, u64 c) {
    u64 d; asm("fma.rn.f32x2 %0, %1, %2, %3;" : "=l"(d) : "l"(a), "l"(b), "l"(c)); return d;
}
__device__ __forceinline__ u64 add2(u64 a, u64 b) {
    u64 d; asm("add.rn.f32x2 %0, %1, %2;" : "=l"(d) : "l"(a), "l"(b)); return d;
}

struct CP {
    u64 NEG1, E2, HH2, HHb, Cp;
    // phi tree, lane-matched coefficient pairs (coeffs scaled by -log2e):
    //   Q12 = X*(a11,a22) + Xs*(a12,0) + Hh*(a13,a24) + Hs*(a14,a23) + (bm1,bm2)
    //   Q34 = Hh*(a33,a44) + Hs*(a34,0) + (bm3,bm4)
    //   PP  = Hh*Q34 + X*Q12 + (bm0,0);  phiS = PP.lo + PP.hi
    u64 CA, CB, CC, CD, Bm12, CE, CF, Bm34, Cbm0;
    float K1, K2;
};

// One step. delta = sigmoid(phi) = rcp(1 + ex2(phiS)), phiS loop-carried.
// State packed: X = (x1,x2), Hh = (h1,h2).
//   x' = [BASE + HH*kuh] + delta * (HH*kdx) ;  h' = h + delta*dx
// Chain: ex2(16) -> +1(4) -> rcp(16) -> bcast(2) -> fma(4) -> tree(~20).
template<bool ADDSC>
__device__ __forceinline__ void stepP(const CP& c, float w1, float w2,
                                      u64& X, u64& Hh, u64& phiP,
                                      u64& accQ2, float& accR, float& accT)
{
    float plo, phi_; upk(plo, phi_, phiP);
    float phiS = plo + phi_;
    float e = ex2f(phiS);                     // MUFU #1, issues early

    // ---- pre-delta geometry (fills both MUFU shadows) ----
    u64 DX = fma2(Hh, c.NEG1, X);             // (dx1, dx2) = X - H
    float dx1, dx2; upk(dx1, dx2, DX);
    float h1, h2;   upk(h1, h2, Hh);
    float x1s, x2s; upk(x1s, x2s, X);
    u64 Xs = pk(x2s, x1s);                    // swapped pair (also used in tree)

    float kuh = fmaf(c.K2, h2, c.K1 * h1);    // K . x_hat
    float kdx = fmaf(c.K2, dx2, c.K1 * dx1);  // K . (x - x_hat)
    float hkdx = 0.01f * kdx;                 // delta-coefficient of x'

    u64 W  = pk(w1, w2);
    u64 WC = add2(W, c.Cp);                   // + (h^2/2, -h^2)
    u64 T1 = fma2(X, c.E2, WC);               // 0.98*x + w + C
    u64 BASE = fma2(Xs, c.HH2, T1);           // + 0.01*x_swapped
    u64 KUH2 = pk(kuh, kuh);
    u64 BXu  = fma2(KUH2, c.HHb, BASE);       // + HH*kuh (both lanes)
    u64 HKp  = pk(hkdx, hkdx);

    if (ADDSC) {
        accQ2 = fma2(X, X, accQ2);            // packed sum of x^2
        float kx = kuh + kdx;                 // u_s = K . x (exact)
        accR = fmaf(kx, kx, accR);            // 0.1 applied once at the end
    }

    float den   = 1.0f + e;
    float delta = rcpf(den);                  // MUFU #2
    if (ADDSC) accT = accT + delta;           // LAM * delta, off the chain

    // ---- post-rcp: broadcast + one packed FMA per state pair ----
    u64 DEL2 = pk(delta, delta);
    X  = fma2(DEL2, HKp, BXu);
    Hh = fma2(DEL2, DX, Hh);

    // ---- phiS tree for the NEXT step (8 packed fma; pairs for phiP) ----
    float x1, x2; upk(x1, x2, X);
    float g1, g2; upk(g1, g2, Hh);
    u64 Xs2 = pk(x2, x1);
    u64 Hs2 = pk(g2, g1);
    u64 Q34 = fma2(Hh, c.CE, fma2(Hs2, c.CF, c.Bm34));
    u64 Q12 = fma2(X, c.CA,
              fma2(Xs2, c.CB,
              fma2(Hh, c.CC,
              fma2(Hs2, c.CD, c.Bm12))));
    phiP = fma2(Hh, Q34, fma2(X, Q12, c.Cbm0));
}

__global__ void __launch_bounds__(64, 1) cstr_traj_kernel(
    const float* __restrict__ w,   // (B, 2, T)
    const float* __restrict__ K,   // (1, 2)
    const float* __restrict__ L,   // (4, 4)
    const float* __restrict__ M,   // (1, 4)
    const float* __restrict__ Mo,  // (1, 1)
    float* __restrict__ out)       // (B,)
{
    int b = blockIdx.x * blockDim.x + threadIdx.x;

    const float s = -1.44269504088896340736f;  // -log2(e), folded into phi
    float K1 = __ldg(K), K2 = __ldg(K + 1);
    float l[16];
#pragma unroll
    for (int i = 0; i < 16; i++) l[i] = __ldg(L + i);
    float a11 = s * l[0],           a22 = s * l[5];
    float a33 = s * l[10],          a44 = s * l[15];
    float a12 = s * (l[1] + l[4]),  a13 = s * (l[2] + l[8]);
    float a14 = s * (l[3] + l[12]), a23 = s * (l[6] + l[9]);
    float a24 = s * (l[7] + l[13]), a34 = s * (l[11] + l[14]);
    float bm1 = s * __ldg(M),       bm2 = s * __ldg(M + 1);
    float bm3 = s * __ldg(M + 2),   bm4 = s * __ldg(M + 3);
    float bm0 = s * __ldg(Mo);

    CP c;
    c.K1 = K1; c.K2 = K2;
    c.NEG1 = pk(-1.0f, -1.0f);
    c.E2   = pk(0.98f, 0.98f);
    c.HH2  = pk(HH, HH);
    c.HHb  = pk(HH, HH);
    c.Cp   = pk(0.5f * HH * HH, -HH * HH);      // (+h^2/2, -h^2)
    // Lane check (q1,q2): q1 = a11 x1 + a12 x2 + a13 h1 + a14 h2 + bm1
    //                     q2 = a22 x2 +   0 x1 + a24 h2 + a23 h1 + bm2
    c.CA = pk(a11, a22);    // * X  = (x1, x2)
    c.CB = pk(a12, 0.0f);   // * Xs = (x2, x1)
    c.CC = pk(a13, a24);    // * Hh = (h1, h2)
    c.CD = pk(a14, a23);    // * Hs = (h2, h1)
    c.Bm12 = pk(bm1, bm2);
    // (q3,q4): q3 = a33 h1 + a34 h2 + bm3 ; q4 = a44 h2 + 0 h1 + bm4
    c.CE = pk(a33, a44);    // * Hh
    c.CF = pk(a34, 0.0f);   // * Hs
    c.Bm34 = pk(bm3, bm4);
    c.Cbm0 = pk(bm0, 0.0f);

    const float4* w0 = (const float4*)(w + (size_t)b * 2 * TSTEPS);
    const float4* w1 = (const float4*)(w + (size_t)b * 2 * TSTEPS + TSTEPS);

    u64 X  = pk(1.0f, 0.0f);
    u64 Hh = pk(1.0f, 0.0f);
    u64 accQ2 = pk(0.0f, 0.0f);
    float accR = 0.0f, accT = 0.0f;
    // Step 0: reference forces delta=1 with x_hat frozen. dx==0 makes delta
    // inert in the dynamics; phiS=-200 -> ex2 flushes to 0 -> delta=rcp(1)=1
    // EXACTLY, so accT gets exactly 1.0. No special case, no reconstruction.
    u64 phiP = pk(-200.0f, 0.0f);

    // ---- software prefetch pipeline: PD groups in registers ----
    float4 bA[PD], bB[PD];
#pragma unroll
    for (int d = 0; d < PD; ++d) { bA[d] = w0[d]; bB[d] = w1[d]; }

    // First PD groups (consume slot d, prefetch group PD+d)
#pragma unroll
    for (int d = 0; d < PD; ++d) {
        float4 wa = bA[d], wb = bB[d];
        bA[d] = w0[PD + d]; bB[d] = w1[PD + d];
        stepP<true>(c, wa.x, wb.x, X, Hh, phiP, accQ2, accR, accT);
        stepP<true>(c, wa.y, wb.y, X, Hh, phiP, accQ2, accR, accT);
        stepP<true>(c, wa.z, wb.z, X, Hh, phiP, accQ2, accR, accT);
        stepP<true>(c, wa.w, wb.w, X, Hh, phiP, accQ2, accR, accT);
    }

    // Main: consume slot d = group base+d, prefetch group base+PD+d
    for (int base = PD; base < NG - PD; base += PD) {
#pragma unroll
        for (int d = 0; d < PD; ++d) {
            float4 wa = bA[d], wb = bB[d];
            bA[d] = w0[base + PD + d];
            bB[d] = w1[base + PD + d];
            stepP<true>(c, wa.x, wb.x, X, Hh, phiP, accQ2, accR, accT);
            stepP<true>(c, wa.y, wb.y, X, Hh, phiP, accQ2, accR, accT);
            stepP<true>(c, wa.z, wb.z, X, Hh, phiP, accQ2, accR, accT);
            stepP<true>(c, wa.w, wb.w, X, Hh, phiP, accQ2, accR, accT);
        }
    }

    // Tail: groups NG-PD .. NG-1 from the buffers (static slots)
#pragma unroll
    for (int d = 0; d < PD - 1; ++d) {
        float4 wa = bA[d], wb = bB[d];
        stepP<true>(c, wa.x, wb.x, X, Hh, phiP, accQ2, accR, accT);
        stepP<true>(c, wa.y, wb.y, X, Hh, phiP, accQ2, accR, accT);
        stepP<true>(c, wa.z, wb.z, X, Hh, phiP, accQ2, accR, accT);
        stepP<true>(c, wa.w, wb.w, X, Hh, phiP, accQ2, accR, accT);
    }
    {   // last group: final step (i = T-1) updates state, adds no stage cost
        float4 wa = bA[PD - 1], wb = bB[PD - 1];
        stepP<true >(c, wa.x, wb.x, X, Hh, phiP, accQ2, accR, accT);
        stepP<true >(c, wa.y, wb.y, X, Hh, phiP, accQ2, accR, accT);
        stepP<true >(c, wa.z, wb.z, X, Hh, phiP, accQ2, accR, accT);
        stepP<false>(c, wa.w, wb.w, X, Hh, phiP, accQ2, accR, accT);
    }

    // J = Sigma x^T x + 0.1 Sigma u_s^2 + Sigma delta + terminal 10|x_T|^2
    float aq1, aq2; upk(aq1, aq2, accQ2);
    float J = aq1 + aq2;
    J = fmaf(0.1f, accR, J);
    J = J + accT;
    float x1, x2; upk(x1, x2, X);
    J = fmaf(10.0f * x1, x1, J);
    J = fmaf(10.0f * x2, x2, J);

    if (b < BSIZE) out[b] = J;
}

extern "C" void kernel_launch(void* const* d_in, const int* in_sizes, int n_in,
                              void* d_out, int out_size)
{
    const float* w  = (const float*)d_in[0];
    const float* K  = (const float*)d_in[1];
    const float* L  = (const float*)d_in[2];
    const float* M  = (const float*)d_in[3];
    const float* Mo = (const float*)d_in[4];
    float* out = (float*)d_out;

    // 8192 trajectories, 1 thread each; 128 blocks x 64 threads = 256 warps,
    // one warp per SMSP.
    cstr_traj_kernel<<<BSIZE / 64, 64>>>(w, K, L, M, Mo, out);
}